// round 1
// baseline (speedup 1.0000x reference)
#include <cuda_runtime.h>
#include <cuda_bf16.h>

// LSTMHierarchialAttention2 — output analysis:
//
// The reference ends with:
//     logits = doc @ Wf.T + bf            # shape (1, 1)
//     return jax.nn.softmax(logits, axis=1)
//
// Softmax over a singleton axis is exactly 1.0 for any finite logit
// (e^x / e^x == 1.0f in fp32). The reference's own comment states this:
// "trivially 1.0, faithful to nn.Softmax()".
//
// Therefore BOTH LSTM scans (8192 sequential word steps + 32 sentence
// steps), both attention reductions, and the final linear layer are all
// dead code with respect to the output. The bit-exact correct result is
// the constant 1.0f, independent of every input tensor.
//
// The optimal kernel writes that single float. This is launch-overhead
// bound (~2 us under graph replay) — the true roofline for a constant
// function.

__global__ void lstm_hier_attn_const_kernel(float* __restrict__ out, int n) {
    int i = blockIdx.x * blockDim.x + threadIdx.x;
    if (i < n) {
        out[i] = 1.0f;  // softmax over a 1-element axis
    }
}

extern "C" void kernel_launch(void* const* d_in, const int* in_sizes, int n_in,
                              void* d_out, int out_size) {
    (void)d_in; (void)in_sizes; (void)n_in;
    // out_size is 1 (output shape (1,1), fp32). Keep it general in case the
    // harness pads; every element of the softmax row sums to 1 over axis=1
    // with a single column, so each element is exactly 1.0f.
    float* out = (float*)d_out;
    int threads = 32;
    int blocks = (out_size + threads - 1) / threads;
    if (blocks < 1) blocks = 1;
    lstm_hier_attn_const_kernel<<<blocks, threads>>>(out, out_size);
}

// round 2
// speedup vs baseline: 1.0556x; 1.0556x over previous
#include <cuda_runtime.h>
#include <cuda_bf16.h>

// LSTMHierarchialAttention2 — constant-folded output.
//
// Reference ends with softmax over a singleton axis:
//     logits = doc @ Wf.T + bf            # shape (1, 1)
//     return jax.nn.softmax(logits, axis=1)   # == 1.0 exactly
//
// e^x / e^x == 1.0f for any finite fp32 x, so both LSTM scans, both
// attention reductions, and the final linear are dead code w.r.t. the
// output. Bit-exact result is the constant 1.0f.
//
// R1 measured: passed, rel_err = 0.0, 4.86 us — launch-overhead bound
// (all ncu pipes ~0%). This round strips the kernel to the absolute
// dispatch floor: 1 thread, 1 unconditional 32-bit store, no index math.

__global__ void __launch_bounds__(1) write_one_kernel(float* __restrict__ out) {
    *out = 1.0f;
}

__global__ void write_one_n_kernel(float* __restrict__ out, int n) {
    int i = blockIdx.x * blockDim.x + threadIdx.x;
    if (i < n) out[i] = 1.0f;
}

extern "C" void kernel_launch(void* const* d_in, const int* in_sizes, int n_in,
                              void* d_out, int out_size) {
    (void)d_in; (void)in_sizes; (void)n_in;
    float* out = (float*)d_out;
    if (out_size == 1) {
        // Common (actual) case: output shape (1,1) fp32 — single store,
        // zero control flow on-device.
        write_one_kernel<<<1, 1>>>(out);
    } else {
        // Safety net if the harness ever reports a padded out_size.
        int threads = 128;
        int blocks = (out_size + threads - 1) / threads;
        write_one_n_kernel<<<blocks, threads>>>(out, out_size);
    }
}